// round 9
// baseline (speedup 1.0000x reference)
#include <cuda_runtime.h>
#include <cuda_bf16.h>
#include <cstdint>

#define Bd 8
#define Nd 65536
#define Cd 64
#define Md 64
#define CAP 36
#define Sp 128            // proj splits per batch (8 chunks of 64 n each)
#define TWOPI 6.283185307179586f

typedef unsigned short ush;

// ---------------- device scratch (no allocation; statically zeroed) --------
__device__ float g_rep_fx[CAP], g_rep_fy[CAP];
__device__ int   g_rep_m[CAP], g_rep_pair[CAP];
// [slice = split*2+khalf][b][c][80]
__device__ float g_partial[(size_t)2 * Sp * Bd * Cd * 80];
__device__ ush   g_W[(size_t)Bd * Cd * 160];             // [b][c][160]; pads stay 0

// ---------------- helpers ----------------
__device__ __forceinline__ void splitb(float x, ush& h, ush& l) {
    uint32_t u = __float_as_uint(x);
    h = (ush)(u >> 16);                                   // truncation (exact hi)
    __nv_bfloat16 lb = __float2bfloat16(x - __uint_as_float(u & 0xFFFF0000u));
    l = *reinterpret_cast<ush*>(&lb);
}
__device__ __forceinline__ void trig_of(float2 cc, float fx, float fy,
                                        float& s, float& c) {
    float t = cc.x * fx + cc.y * fy;                      // integer freqs
    float ph = TWOPI * (t - rintf(t));                    // exact reduce to [-pi,pi]
    __sincosf(ph, &s, &c);
}
__device__ __forceinline__ uint32_t pk(ush a, ush b) {
    return (uint32_t)a | ((uint32_t)b << 16);
}
// D(16x8,f32) += A(16x16 row,bf16) * B(16x8 col,bf16)
__device__ __forceinline__ void hmma(float* d, const uint32_t* a, const uint32_t* b) {
    asm volatile(
        "mma.sync.aligned.m16n8k16.row.col.f32.bf16.bf16.f32 "
        "{%0,%1,%2,%3},{%4,%5,%6,%7},{%8,%9},{%0,%1,%2,%3};"
        : "+f"(d[0]), "+f"(d[1]), "+f"(d[2]), "+f"(d[3])
        : "r"(a[0]), "r"(a[1]), "r"(a[2]), "r"(a[3]), "r"(b[0]), "r"(b[1]));
}

// ---------------------------------------------------------------------------
// K0: conjugate-pair discovery (serial, deterministic)
// ---------------------------------------------------------------------------
__global__ void setup_kernel(const float* __restrict__ freqs) {
    if (threadIdx.x != 0 || blockIdx.x != 0) return;
    bool used[Md]; int cnt = 0;
    for (int m = 0; m < Md; m++) used[m] = false;
    for (int m = 0; m < Md; m++) {
        if (used[m]) continue;
        float fx = freqs[2 * m], fy = freqs[2 * m + 1];
        int p = -1;
        for (int q = m + 1; q < Md; q++)
            if (!used[q] && freqs[2 * q] == -fx && freqs[2 * q + 1] == -fy) { p = q; break; }
        if (cnt < CAP) {
            g_rep_m[cnt] = m; g_rep_pair[cnt] = p;
            g_rep_fx[cnt] = fx; g_rep_fy[cnt] = fy; cnt++;
        }
        used[m] = true; if (p >= 0) used[p] = true;
    }
    for (int j = cnt; j < CAP; j++) {
        g_rep_m[j] = -1; g_rep_pair[j] = -1; g_rep_fx[j] = 0.f; g_rep_fy[j] = 0.f;
    }
}

// ---------------------------------------------------------------------------
// K1 proj: D[c(64)][j2(80)] += X[c][k] * T[j2][k]  over n, bf16 hi/lo.
// warp = (c-half m32, j2-half 5xn8, k-half 6 of 12 ksteps); partials per k-half.
// smem: Xs[64][136]h | Ts[80][136]h | xs[64][68]f | sco[64]f2
// ---------------------------------------------------------------------------
#define PSTR 136
#define PSTRW 68
#define TS_OFF (64 * PSTR)
#define XSF_OFF (144 * PSTR * 2)
#define SCO_OFF (XSF_OFF + 64 * 68 * 4)
#define PROJ_SMEM (SCO_OFF + 64 * 8)

__global__ __launch_bounds__(256) void proj_kernel(
    const float* __restrict__ inputs, const float* __restrict__ coords)
{
    extern __shared__ __align__(16) ush sm[];
    uint32_t* Xw = (uint32_t*)sm;
    uint32_t* Tw = (uint32_t*)(sm + TS_OFF);
    float (*xs)[68] = (float(*)[68])((char*)sm + XSF_OFF);
    float2* sco = (float2*)((char*)sm + SCO_OFF);

    const int tid = threadIdx.x, wid = tid >> 5, lane = tid & 31;
    const int g = lane >> 2, tq = lane & 3;
    const int split = blockIdx.x, b = blockIdx.y;
    const int ks = wid & 1;                 // k-half
    const int jh = (wid >> 1) & 1;          // j2 half (5 n8 tiles)
    const int ch = wid >> 2;                // c half (m32)

    // zero T tile once (rows 72-79 must stay zero)
    for (int i = tid; i < 80 * PSTRW; i += 256) Tw[i] = 0;

    float acc[2][5][4];
    #pragma unroll
    for (int t = 0; t < 2; t++)
        #pragma unroll
        for (int u = 0; u < 5; u++)
            #pragma unroll
            for (int v = 0; v < 4; v++) acc[t][u][v] = 0.f;

    const int nbase = split * (Nd / Sp);
    const float2* cin = ((const float2*)coords) + (size_t)b * Nd;

    for (int t = 0; t < (Nd / Sp) / 64; t++) {
        const int n0 = nbase + t * 64;
        __syncthreads();                     // tiles & xs free
        // stage x [64n][64c]
        const float4* xin4 = (const float4*)(inputs + ((size_t)b * Nd + n0) * Cd);
        #pragma unroll
        for (int r = 0; r < 4; r++) {
            const int idx = tid + 256 * r;
            const float4 v = xin4[idx];
            *(float4*)&xs[idx >> 4][(idx & 15) << 2] = v;
        }
        if (tid < 64) sco[tid] = cin[n0 + tid];
        __syncthreads();

        // X tile: c = tid>>2, n = 2q + 8i
        {
            const int c = tid >> 2, q = tid & 3;
            #pragma unroll
            for (int i = 0; i < 8; i++) {
                const int n = 2 * q + 8 * i;
                ush h0, l0, h1, l1;
                splitb(xs[n][c], h0, l0);
                splitb(xs[n + 1][c], h1, l1);
                Xw[c * PSTRW + (n >> 1)]      = pk(h0, h1);
                Xw[c * PSTRW + 32 + (n >> 1)] = pk(l0, l1);
            }
        }
        // T tile: 1152 (j, n-pair) items
        for (int e = tid; e < 1152; e += 256) {
            const int j = e >> 5, n = (e & 31) * 2;
            const float fx = g_rep_fx[j], fy = g_rep_fy[j];
            float s0, c0, s1, c1;
            trig_of(sco[n], fx, fy, s0, c0);
            trig_of(sco[n + 1], fx, fy, s1, c1);
            ush ch0, cl0, sh0, sl0, ch1, cl1, sh1, sl1;
            splitb(c0, ch0, cl0); splitb(s0, sh0, sl0);
            splitb(c1, ch1, cl1); splitb(s1, sh1, sl1);
            Tw[j * PSTRW + (n >> 1)]             = pk(ch0, ch1);
            Tw[j * PSTRW + 32 + (n >> 1)]        = pk(cl0, cl1);
            Tw[(36 + j) * PSTRW + (n >> 1)]      = pk(sh0, sh1);
            Tw[(36 + j) * PSTRW + 32 + (n >> 1)] = pk(sl0, sl1);
        }
        __syncthreads();

        // my 6 of 12 ksteps (3 product groups x 4)
        #pragma unroll
        for (int q = 0; q < 6; q++) {
            const int s = ks * 6 + q;
            const int gr = s >> 2, s4 = s & 3;
            const int kwA = ((gr == 1) ? 32 : 0) + 8 * s4;   // X lo for group 1
            const int kwB = ((gr == 2) ? 32 : 0) + 8 * s4;   // T lo for group 2
            uint32_t a[2][4];
            #pragma unroll
            for (int tt = 0; tt < 2; tt++) {
                const int ra = (ch * 32 + tt * 16 + g) * PSTRW + kwA + tq;
                a[tt][0] = Xw[ra];              a[tt][1] = Xw[ra + 8 * PSTRW];
                a[tt][2] = Xw[ra + 4];          a[tt][3] = Xw[ra + 8 * PSTRW + 4];
            }
            #pragma unroll
            for (int u = 0; u < 5; u++) {
                uint32_t bb[2];
                const int rb = ((jh * 5 + u) * 8 + g) * PSTRW + kwB + tq;
                bb[0] = Tw[rb]; bb[1] = Tw[rb + 4];
                hmma(acc[0][u], a[0], bb);
                hmma(acc[1][u], a[1], bb);
            }
        }
    }

    // epilogue -> slice (split*2 + ks)
    float* dst = g_partial + (((size_t)(split * 2 + ks) * Bd + b) * Cd) * 80;
    #pragma unroll
    for (int tt = 0; tt < 2; tt++) {
        #pragma unroll
        for (int u = 0; u < 5; u++) {
            const int j = (jh * 5 + u) * 8 + 2 * tq;
            const int c0 = ch * 32 + tt * 16 + g;
            *(float2*)&dst[(size_t)c0 * 80 + j]       = make_float2(acc[tt][u][0], acc[tt][u][1]);
            *(float2*)&dst[(size_t)(c0 + 8) * 80 + j] = make_float2(acc[tt][u][2], acc[tt][u][3]);
        }
    }
}

// ---------------------------------------------------------------------------
// K2 mix: reduce 2*Sp slices (coalesced, j fastest), weight + conj fold -> bf16 W
// ---------------------------------------------------------------------------
__global__ __launch_bounds__(256) void mix_kernel(
    const float* __restrict__ wre, const float* __restrict__ wim)
{
    const int idx = blockIdx.x * 256 + threadIdx.x;       // Bd*64*36
    const int b = idx / (Cd * CAP);
    const int rem = idx - b * (Cd * CAP);
    const int c = rem / CAP, j = rem - c * CAP;
    const int m = g_rep_m[j];
    if (m < 0) return;

    float cr = 0.f, si = 0.f;
    #pragma unroll 4
    for (int s = 0; s < 2 * Sp; s++) {
        const float* p = g_partial + (((size_t)s * Bd + b) * Cd + c) * 80;
        cr += p[j];
        si += p[36 + j];
    }
    const float ci = -si, inv = 1.0f / (float)Nd;
    const float wr = wre[m * Cd + c], wi = wim[m * Cd + c];
    float A2 =  (cr * wr - ci * wi) * inv;
    float B2 = -(cr * wi + ci * wr) * inv;
    const int pp = g_rep_pair[j];
    if (pp >= 0) {
        const float wrp = wre[pp * Cd + c], wip = wim[pp * Cd + c];
        A2 += ( cr * wrp + ci * wip) * inv;
        B2 -= (-cr * wip + ci * wrp) * inv;
    }
    ush ah, al, bh, bl;
    splitb(A2, ah, al); splitb(B2, bh, bl);
    ush* W = g_W + ((size_t)b * Cd + c) * 160;
    W[j] = ah; W[36 + j] = bh; W[80 + j] = al; W[116 + j] = bl;
}

// ---------------------------------------------------------------------------
// K3 recon: D[n(256)][c(64)] = T[n][k] * W[c][k]; warp = m32 x full n=64c.
// smem: Ts[256][168]h | Ws[64][168]h
// ---------------------------------------------------------------------------
#define RSTR 168
#define RSTRW 84
#define WS_OFF (256 * RSTR)
#define RECON_SMEM ((256 + 64) * RSTR * 2)

__global__ __launch_bounds__(256, 2) void recon_kernel(
    const float* __restrict__ coords, float* __restrict__ out)
{
    extern __shared__ __align__(16) ush sm[];
    ush* Ts = sm;
    ush* Ws = sm + WS_OFF;
    uint32_t* Twr = (uint32_t*)Ts;
    uint32_t* Wwr = (uint32_t*)Ws;

    const int tid = threadIdx.x, wid = tid >> 5, lane = tid & 31;
    const int g = lane >> 2, tq = lane & 3;
    const int b = blockIdx.y, n0 = blockIdx.x * 256;

    // zero Ts pad words: hi-pad 36..39 (halves 72..79) AND lo-pad 76..79
    // (halves 152..159) — BOTH are read by the kstep loops.  One row/thread.
    {
        uint32_t* r = Twr + tid * RSTRW;
        r[36] = 0; r[37] = 0; r[38] = 0; r[39] = 0;
        r[76] = 0; r[77] = 0; r[78] = 0; r[79] = 0;
    }
    // W tile: 64 rows x 20 uint4 (g_W pads are statically zero)
    for (int v = tid; v < 1280; v += 256) {
        const int c = v / 20, q2 = v - c * 20;
        const uint4 w = *(const uint4*)(g_W + ((size_t)b * Cd + c) * 160 + q2 * 8);
        *(uint4*)&Ws[c * RSTR + q2 * 8] = w;
    }
    // T tile: items (n, jw): packed STS.32, jw-major
    {
        const float2* cbase = ((const float2*)coords) + (size_t)b * Nd + n0;
        #pragma unroll
        for (int i = 0; i < 18; i++) {
            const int e = tid + 256 * i;              // 0..4607
            const int n = e / 18, jw = e - n * 18;
            const float2 cc = cbase[n];
            const int j0 = 2 * jw, j1 = j0 + 1;
            float s0, c0, s1, c1;
            trig_of(cc, g_rep_fx[j0], g_rep_fy[j0], s0, c0);
            trig_of(cc, g_rep_fx[j1], g_rep_fy[j1], s1, c1);
            ush ch0, cl0, sh0, sl0, ch1, cl1, sh1, sl1;
            splitb(c0, ch0, cl0); splitb(s0, sh0, sl0);
            splitb(c1, ch1, cl1); splitb(s1, sh1, sl1);
            uint32_t* r = Twr + n * RSTRW;
            r[jw]      = pk(ch0, ch1);
            r[18 + jw] = pk(sh0, sh1);
            r[40 + jw] = pk(cl0, cl1);
            r[58 + jw] = pk(sl0, sl1);
        }
    }
    __syncthreads();

    float acc[2][8][4];
    #pragma unroll
    for (int t = 0; t < 2; t++)
        #pragma unroll
        for (int u = 0; u < 8; u++)
            #pragma unroll
            for (int v = 0; v < 4; v++) acc[t][u][v] = 0.f;

    // 15 ksteps = 3 groups x 5; warp m32 tile shares A across all 8 B tiles
    #pragma unroll
    for (int s = 0; s < 15; s++) {
        const int gr = s / 5, s5 = s - gr * 5;
        const int kwA = ((gr == 1) ? 40 : 0) + 8 * s5;   // T lo for group 1
        const int kwB = ((gr == 2) ? 40 : 0) + 8 * s5;   // W lo for group 2
        uint32_t a[2][4];
        #pragma unroll
        for (int tt = 0; tt < 2; tt++) {
            const int ra = (wid * 32 + tt * 16 + g) * RSTRW + kwA + tq;
            a[tt][0] = Twr[ra];              a[tt][1] = Twr[ra + 8 * RSTRW];
            a[tt][2] = Twr[ra + 4];          a[tt][3] = Twr[ra + 8 * RSTRW + 4];
        }
        #pragma unroll
        for (int u = 0; u < 8; u++) {
            uint32_t bb[2];
            const int rb = (u * 8 + g) * RSTRW + kwB + tq;
            bb[0] = Wwr[rb]; bb[1] = Wwr[rb + 4];
            hmma(acc[0][u], a[0], bb);
            hmma(acc[1][u], a[1], bb);
        }
    }

    // epilogue
    #pragma unroll
    for (int tt = 0; tt < 2; tt++) {
        const int r0 = wid * 32 + tt * 16 + g;
        float* o0 = out + ((size_t)b * Nd + n0 + r0) * Cd;
        float* o1 = o0 + 8 * Cd;
        #pragma unroll
        for (int u = 0; u < 8; u++) {
            const int c = u * 8 + 2 * tq;
            *(float2*)&o0[c] = make_float2(acc[tt][u][0], acc[tt][u][1]);
            *(float2*)&o1[c] = make_float2(acc[tt][u][2], acc[tt][u][3]);
        }
    }
}

// ---------------------------------------------------------------------------
extern "C" void kernel_launch(void* const* d_in, const int* in_sizes, int n_in,
                              void* d_out, int out_size)
{
    const float* inputs = (const float*)d_in[0];
    const float* coords = (const float*)d_in[1];
    const float* wre    = (const float*)d_in[2];
    const float* wim    = (const float*)d_in[3];
    const float* freqs  = (const float*)d_in[4];
    float* out = (float*)d_out;

    cudaFuncSetAttribute(proj_kernel,  cudaFuncAttributeMaxDynamicSharedMemorySize, PROJ_SMEM);
    cudaFuncSetAttribute(recon_kernel, cudaFuncAttributeMaxDynamicSharedMemorySize, RECON_SMEM);

    setup_kernel<<<1, 32>>>(freqs);
    proj_kernel<<<dim3(Sp, Bd), 256, PROJ_SMEM>>>(inputs, coords);
    mix_kernel<<<(Bd * Cd * CAP) / 256, 256>>>(wre, wim);
    recon_kernel<<<dim3(Nd / 256, Bd), 256, RECON_SMEM>>>(coords, out);
}

// round 11
// speedup vs baseline: 1.2496x; 1.2496x over previous
#include <cuda_runtime.h>
#include <cuda_bf16.h>
#include <cstdint>

#define Bd 8
#define Nd 65536
#define Cd 64
#define Md 64
#define CAP 36
#define Sp 256            // proj splits per batch (4 chunks of 64 n each)
#define PCHUNKS ((Nd / Sp) / 64)
#define SLICE (Bd * Cd * 80)
#define TWOPI 6.283185307179586f

typedef unsigned short ush;

// ---------------- device scratch (no allocation; statically zeroed) --------
__device__ float g_rep_fx[CAP], g_rep_fy[CAP];
__device__ int   g_rep_m[CAP], g_rep_pair[CAP];
__device__ float g_partial[(size_t)Sp * SLICE];          // [split][b][c][80]
__device__ float g_red[(size_t)8 * SLICE];               // [8][b][c][80]
__device__ ush   g_W[(size_t)Bd * Cd * 160];             // [b][c][160]; pads stay 0

// ---------------- helpers ----------------
__device__ __forceinline__ void splitb(float x, ush& h, ush& l) {
    uint32_t u = __float_as_uint(x);
    h = (ush)(u >> 16);                                   // truncation (exact hi)
    __nv_bfloat16 lb = __float2bfloat16(x - __uint_as_float(u & 0xFFFF0000u));
    l = *reinterpret_cast<ush*>(&lb);
}
__device__ __forceinline__ void trig_of(float2 cc, float fx, float fy,
                                        float& s, float& c) {
    float t = cc.x * fx + cc.y * fy;                      // integer freqs
    float ph = TWOPI * (t - rintf(t));                    // exact reduce to [-pi,pi]
    __sincosf(ph, &s, &c);
}
__device__ __forceinline__ uint32_t pk(ush a, ush b) {
    return (uint32_t)a | ((uint32_t)b << 16);
}
// D(16x8,f32) += A(16x16 row,bf16) * B(16x8 col,bf16)
__device__ __forceinline__ void hmma(float* d, const uint32_t* a, const uint32_t* b) {
    asm volatile(
        "mma.sync.aligned.m16n8k16.row.col.f32.bf16.bf16.f32 "
        "{%0,%1,%2,%3},{%4,%5,%6,%7},{%8,%9},{%0,%1,%2,%3};"
        : "+f"(d[0]), "+f"(d[1]), "+f"(d[2]), "+f"(d[3])
        : "r"(a[0]), "r"(a[1]), "r"(a[2]), "r"(a[3]), "r"(b[0]), "r"(b[1]));
}

// ---------------------------------------------------------------------------
// K0: conjugate-pair discovery (serial, deterministic)
// ---------------------------------------------------------------------------
__global__ void setup_kernel(const float* __restrict__ freqs) {
    if (threadIdx.x != 0 || blockIdx.x != 0) return;
    bool used[Md]; int cnt = 0;
    for (int m = 0; m < Md; m++) used[m] = false;
    for (int m = 0; m < Md; m++) {
        if (used[m]) continue;
        float fx = freqs[2 * m], fy = freqs[2 * m + 1];
        int p = -1;
        for (int q = m + 1; q < Md; q++)
            if (!used[q] && freqs[2 * q] == -fx && freqs[2 * q + 1] == -fy) { p = q; break; }
        if (cnt < CAP) {
            g_rep_m[cnt] = m; g_rep_pair[cnt] = p;
            g_rep_fx[cnt] = fx; g_rep_fy[cnt] = fy; cnt++;
        }
        used[m] = true; if (p >= 0) used[p] = true;
    }
    for (int j = cnt; j < CAP; j++) {
        g_rep_m[j] = -1; g_rep_pair[j] = -1; g_rep_fx[j] = 0.f; g_rep_fy[j] = 0.f;
    }
}

// ---------------------------------------------------------------------------
// K1 proj: D[c(64)][j2(80)] += X[c][k] * T[j2][k]  over n, bf16 hi/lo.
// (R7 structure: warp = c-tile m16 x j2-half, all 12 ksteps)
// smem: Xs[64][136]h | Ts[80][136]h | xs[64][68]f | sco[64]f2
// ---------------------------------------------------------------------------
#define PSTR 136
#define PSTRW 68
#define TS_OFF (64 * PSTR)
#define XSF_OFF (144 * PSTR * 2)
#define SCO_OFF (XSF_OFF + 64 * 68 * 4)
#define PROJ_SMEM (SCO_OFF + 64 * 8)

__global__ __launch_bounds__(256) void proj_kernel(
    const float* __restrict__ inputs, const float* __restrict__ coords)
{
    extern __shared__ __align__(16) ush sm[];
    uint32_t* Xw = (uint32_t*)sm;
    uint32_t* Tw = (uint32_t*)(sm + TS_OFF);
    float (*xs)[68] = (float(*)[68])((char*)sm + XSF_OFF);
    float2* sco = (float2*)((char*)sm + SCO_OFF);

    const int tid = threadIdx.x, wid = tid >> 5, lane = tid & 31;
    const int g = lane >> 2, tq = lane & 3;
    const int split = blockIdx.x, b = blockIdx.y;

    // zero T tile once (rows 72-79 must stay zero)
    for (int i = tid; i < 80 * PSTRW; i += 256) Tw[i] = 0;

    const int mt = wid >> 1;                 // c tile: c0 = mt*16
    const int nb = (wid & 1) * 5;            // j2 tiles nb..nb+4

    float acc[5][4];
    #pragma unroll
    for (int u = 0; u < 5; u++)
        #pragma unroll
        for (int v = 0; v < 4; v++) acc[u][v] = 0.f;

    const int nbase = split * (Nd / Sp);
    const float2* cin = ((const float2*)coords) + (size_t)b * Nd;

    for (int t = 0; t < PCHUNKS; t++) {
        const int n0 = nbase + t * 64;
        __syncthreads();                     // tiles & xs free
        // stage x [64n][64c]
        const float4* xin4 = (const float4*)(inputs + ((size_t)b * Nd + n0) * Cd);
        #pragma unroll
        for (int r = 0; r < 4; r++) {
            const int idx = tid + 256 * r;
            const float4 v = xin4[idx];
            *(float4*)&xs[idx >> 4][(idx & 15) << 2] = v;
        }
        if (tid < 64) sco[tid] = cin[n0 + tid];
        __syncthreads();

        // X tile: c = tid>>2, n = 2q + 8i (conflict-free column reads)
        {
            const int c = tid >> 2, q = tid & 3;
            #pragma unroll
            for (int i = 0; i < 8; i++) {
                const int n = 2 * q + 8 * i;
                ush h0, l0, h1, l1;
                splitb(xs[n][c], h0, l0);
                splitb(xs[n + 1][c], h1, l1);
                Xw[c * PSTRW + (n >> 1)]      = pk(h0, h1);
                Xw[c * PSTRW + 32 + (n >> 1)] = pk(l0, l1);
            }
        }
        // T tile: 1152 (j, n-pair) items
        for (int e = tid; e < 1152; e += 256) {
            const int j = e >> 5, n = (e & 31) * 2;
            const float fx = g_rep_fx[j], fy = g_rep_fy[j];
            float s0, c0, s1, c1;
            trig_of(sco[n], fx, fy, s0, c0);
            trig_of(sco[n + 1], fx, fy, s1, c1);
            ush ch0, cl0, sh0, sl0, ch1, cl1, sh1, sl1;
            splitb(c0, ch0, cl0); splitb(s0, sh0, sl0);
            splitb(c1, ch1, cl1); splitb(s1, sh1, sl1);
            Tw[j * PSTRW + (n >> 1)]             = pk(ch0, ch1);
            Tw[j * PSTRW + 32 + (n >> 1)]        = pk(cl0, cl1);
            Tw[(36 + j) * PSTRW + (n >> 1)]      = pk(sh0, sh1);
            Tw[(36 + j) * PSTRW + 32 + (n >> 1)] = pk(sl0, sl1);
        }
        __syncthreads();

        // MMA: 12 ksteps = 3 product groups x 4
        #pragma unroll
        for (int gr = 0; gr < 3; gr++) {
            const int kwAb = (gr == 1) ? 32 : 0;     // X lo for group 1
            const int kwBb = (gr == 2) ? 32 : 0;     // T lo for group 2
            #pragma unroll
            for (int s = 0; s < 4; s++) {
                const int kwA = kwAb + 8 * s, kwB = kwBb + 8 * s;
                uint32_t a[4];
                const int ra = (mt * 16 + g) * PSTRW + kwA + tq;
                a[0] = Xw[ra];              a[1] = Xw[ra + 8 * PSTRW];
                a[2] = Xw[ra + 4];          a[3] = Xw[ra + 8 * PSTRW + 4];
                #pragma unroll
                for (int u = 0; u < 5; u++) {
                    uint32_t bb[2];
                    const int rb = ((nb + u) * 8 + g) * PSTRW + kwB + tq;
                    bb[0] = Tw[rb]; bb[1] = Tw[rb + 4];
                    hmma(acc[u], a, bb);
                }
            }
        }
    }

    // epilogue: D[c][j2] -> g_partial[split][b][c][80]
    float* dst = g_partial + (((size_t)split * Bd + b) * Cd) * 80;
    #pragma unroll
    for (int u = 0; u < 5; u++) {
        const int j = (nb + u) * 8 + 2 * tq;
        const int c0 = mt * 16 + g;
        *(float2*)&dst[(size_t)c0 * 80 + j]       = make_float2(acc[u][0], acc[u][1]);
        *(float2*)&dst[(size_t)(c0 + 8) * 80 + j] = make_float2(acc[u][2], acc[u][3]);
    }
}

// ---------------------------------------------------------------------------
// K2a: parallel reduce 256 slices -> 8 (coalesced; deterministic grouping)
// ---------------------------------------------------------------------------
__global__ __launch_bounds__(256) void reduce_kernel() {
    const int idx = blockIdx.x * 256 + threadIdx.x;       // over 8*SLICE
    const int r8 = idx / SLICE;
    const int rem = idx - r8 * SLICE;
    const float* p = g_partial + (size_t)r8 * 32 * SLICE + rem;
    float s = 0.f;
    #pragma unroll 8
    for (int i = 0; i < 32; i++) s += p[(size_t)i * SLICE];
    g_red[idx] = s;
}

// ---------------------------------------------------------------------------
// K2b mix: reduce 8 slices, 1/N + weight + conj fold, emit bf16 hi/lo W
// ---------------------------------------------------------------------------
__global__ __launch_bounds__(256) void mix_kernel(
    const float* __restrict__ wre, const float* __restrict__ wim)
{
    const int idx = blockIdx.x * 256 + threadIdx.x;       // Bd*64*36
    const int b = idx / (Cd * CAP);
    const int rem = idx - b * (Cd * CAP);
    const int c = rem / CAP, j = rem - c * CAP;
    const int m = g_rep_m[j];
    if (m < 0) return;

    float cr = 0.f, si = 0.f;
    const float* p = g_red + ((size_t)b * Cd + c) * 80;
    #pragma unroll
    for (int s = 0; s < 8; s++) {
        cr += p[(size_t)s * SLICE + j];
        si += p[(size_t)s * SLICE + 36 + j];
    }
    const float ci = -si, inv = 1.0f / (float)Nd;
    const float wr = wre[m * Cd + c], wi = wim[m * Cd + c];
    float A2 =  (cr * wr - ci * wi) * inv;
    float B2 = -(cr * wi + ci * wr) * inv;
    const int pp = g_rep_pair[j];
    if (pp >= 0) {
        const float wrp = wre[pp * Cd + c], wip = wim[pp * Cd + c];
        A2 += ( cr * wrp + ci * wip) * inv;
        B2 -= (-cr * wip + ci * wrp) * inv;
    }
    ush ah, al, bh, bl;
    splitb(A2, ah, al); splitb(B2, bh, bl);
    ush* W = g_W + ((size_t)b * Cd + c) * 160;
    W[j] = ah; W[36 + j] = bh; W[80 + j] = al; W[116 + j] = bl;
}

// ---------------------------------------------------------------------------
// K3 recon: D[n(128)][c(64)] = T[n][k] * W[c][k]  (R7 m16 structure)
// smem: Ts[128][168]h | Ws[64][168]h
// ---------------------------------------------------------------------------
#define RSTR 168
#define RSTRW 84
#define WS_OFF (128 * RSTR)
#define RECON_SMEM ((128 + 64) * RSTR * 2)

__global__ __launch_bounds__(256, 2) void recon_kernel(
    const float* __restrict__ coords, float* __restrict__ out)
{
    extern __shared__ __align__(16) ush sm[];
    ush* Ws = sm + WS_OFF;
    uint32_t* Twr = (uint32_t*)sm;
    uint32_t* Wwr = (uint32_t*)Ws;

    const int tid = threadIdx.x, wid = tid >> 5, lane = tid & 31;
    const int g = lane >> 2, tq = lane & 3;
    const int b = blockIdx.y, n0 = blockIdx.x * 128;

    // zero Ts pad words: hi-pad 36..39 (halves 72..79) AND lo-pad 76..79
    // (halves 152..159) — both are read by the kstep loops.
    if (tid < 128) {
        uint32_t* r = Twr + tid * RSTRW;
        r[36] = 0; r[37] = 0; r[38] = 0; r[39] = 0;
        r[76] = 0; r[77] = 0; r[78] = 0; r[79] = 0;
    }
    // W tile: 64 rows x 20 uint4 (g_W pads are statically zero)
    for (int v = tid; v < 1280; v += 256) {
        const int c = v / 20, q2 = v - c * 20;
        const uint4 w = *(const uint4*)(g_W + ((size_t)b * Cd + c) * 160 + q2 * 8);
        *(uint4*)&Ws[c * RSTR + q2 * 8] = w;
    }
    // T tile: packed STS.32, jw-major: 128 n x 18 mode-pair words
    {
        const float2* cbase = ((const float2*)coords) + (size_t)b * Nd + n0;
        #pragma unroll
        for (int i = 0; i < 9; i++) {
            const int e = tid + 256 * i;              // 0..2303
            const int n = e / 18, jw = e - n * 18;
            const float2 cc = cbase[n];
            const int j0 = 2 * jw, j1 = j0 + 1;
            float s0, c0, s1, c1;
            trig_of(cc, g_rep_fx[j0], g_rep_fy[j0], s0, c0);
            trig_of(cc, g_rep_fx[j1], g_rep_fy[j1], s1, c1);
            ush ch0, cl0, sh0, sl0, ch1, cl1, sh1, sl1;
            splitb(c0, ch0, cl0); splitb(s0, sh0, sl0);
            splitb(c1, ch1, cl1); splitb(s1, sh1, sl1);
            uint32_t* r = Twr + n * RSTRW;
            r[jw]      = pk(ch0, ch1);
            r[18 + jw] = pk(sh0, sh1);
            r[40 + jw] = pk(cl0, cl1);
            r[58 + jw] = pk(sl0, sl1);
        }
    }
    __syncthreads();

    float acc[8][4];
    #pragma unroll
    for (int u = 0; u < 8; u++)
        #pragma unroll
        for (int v = 0; v < 4; v++) acc[u][v] = 0.f;

    // 15 ksteps = 3 groups x 5
    #pragma unroll
    for (int s = 0; s < 15; s++) {
        const int gr = s / 5, s5 = s - gr * 5;
        const int kwA = ((gr == 1) ? 40 : 0) + 8 * s5;   // T lo for group 1
        const int kwB = ((gr == 2) ? 40 : 0) + 8 * s5;   // W lo for group 2
        uint32_t a[4];
        const int ra = (wid * 16 + g) * RSTRW + kwA + tq;
        a[0] = Twr[ra];             a[1] = Twr[ra + 8 * RSTRW];
        a[2] = Twr[ra + 4];         a[3] = Twr[ra + 8 * RSTRW + 4];
        #pragma unroll
        for (int u = 0; u < 8; u++) {
            uint32_t bb[2];
            const int rb = (u * 8 + g) * RSTRW + kwB + tq;
            bb[0] = Wwr[rb]; bb[1] = Wwr[rb + 4];
            hmma(acc[u], a, bb);
        }
    }

    // epilogue: D[n][c] -> out
    const int r0 = wid * 16 + g;
    float* o0 = out + ((size_t)b * Nd + n0 + r0) * Cd;
    float* o1 = o0 + 8 * Cd;
    #pragma unroll
    for (int u = 0; u < 8; u++) {
        const int c = u * 8 + 2 * tq;
        *(float2*)&o0[c] = make_float2(acc[u][0], acc[u][1]);
        *(float2*)&o1[c] = make_float2(acc[u][2], acc[u][3]);
    }
}

// ---------------------------------------------------------------------------
extern "C" void kernel_launch(void* const* d_in, const int* in_sizes, int n_in,
                              void* d_out, int out_size)
{
    const float* inputs = (const float*)d_in[0];
    const float* coords = (const float*)d_in[1];
    const float* wre    = (const float*)d_in[2];
    const float* wim    = (const float*)d_in[3];
    const float* freqs  = (const float*)d_in[4];
    float* out = (float*)d_out;

    cudaFuncSetAttribute(proj_kernel,  cudaFuncAttributeMaxDynamicSharedMemorySize, PROJ_SMEM);
    cudaFuncSetAttribute(recon_kernel, cudaFuncAttributeMaxDynamicSharedMemorySize, RECON_SMEM);

    setup_kernel<<<1, 32>>>(freqs);
    proj_kernel<<<dim3(Sp, Bd), 256, PROJ_SMEM>>>(inputs, coords);
    reduce_kernel<<<(8 * SLICE) / 256, 256>>>();
    mix_kernel<<<(Bd * Cd * CAP) / 256, 256>>>(wre, wim);
    recon_kernel<<<dim3(Nd / 128, Bd), 256, RECON_SMEM>>>(coords, out);
}

// round 12
// speedup vs baseline: 1.2548x; 1.0041x over previous
#include <cuda_runtime.h>
#include <cuda_bf16.h>
#include <cstdint>

#define Bd 8
#define Nd 65536
#define Cd 64
#define Md 64
#define CAP 36
#define Sp 512            // proj splits per batch (2 chunks of 64 n each)
#define PCHUNKS ((Nd / Sp) / 64)
#define SLICE (Bd * Cd * 80)
#define TWOPI 6.283185307179586f

typedef unsigned short ush;

// ---------------- device scratch (no allocation; statically zeroed) --------
__device__ float g_rep_fx[CAP], g_rep_fy[CAP];
__device__ int   g_rep_m[CAP], g_rep_pair[CAP];
__device__ float g_partial[(size_t)Sp * SLICE];          // [split][b][c][80]
__device__ float g_red[(size_t)8 * SLICE];               // [8][b][c][80]
__device__ ush   g_W[(size_t)Bd * Cd * 160];             // [b][c][160]; pads stay 0

// ---------------- helpers ----------------
__device__ __forceinline__ void splitb(float x, ush& h, ush& l) {
    uint32_t u = __float_as_uint(x);
    h = (ush)(u >> 16);                                   // truncation (exact hi)
    __nv_bfloat16 lb = __float2bfloat16(x - __uint_as_float(u & 0xFFFF0000u));
    l = *reinterpret_cast<ush*>(&lb);
}
__device__ __forceinline__ void trig_of(float2 cc, float fx, float fy,
                                        float& s, float& c) {
    float t = cc.x * fx + cc.y * fy;                      // integer freqs
    float ph = TWOPI * (t - rintf(t));                    // exact reduce to [-pi,pi]
    __sincosf(ph, &s, &c);
}
__device__ __forceinline__ uint32_t pk(ush a, ush b) {
    return (uint32_t)a | ((uint32_t)b << 16);
}
// D(16x8,f32) += A(16x16 row,bf16) * B(16x8 col,bf16)
__device__ __forceinline__ void hmma(float* d, const uint32_t* a, const uint32_t* b) {
    asm volatile(
        "mma.sync.aligned.m16n8k16.row.col.f32.bf16.bf16.f32 "
        "{%0,%1,%2,%3},{%4,%5,%6,%7},{%8,%9},{%0,%1,%2,%3};"
        : "+f"(d[0]), "+f"(d[1]), "+f"(d[2]), "+f"(d[3])
        : "r"(a[0]), "r"(a[1]), "r"(a[2]), "r"(a[3]), "r"(b[0]), "r"(b[1]));
}

// ---------------------------------------------------------------------------
// K0: conjugate-pair discovery (parallel pair search; deterministic rep
// order identical to the serial scan: m is a rep iff pair(m) > m or none).
// ---------------------------------------------------------------------------
__global__ void setup_kernel(const float* __restrict__ freqs) {
    __shared__ float sfx[Md], sfy[Md];
    __shared__ int sp[Md];
    const int m = threadIdx.x;                 // 64 threads
    const float fx = freqs[2 * m], fy = freqs[2 * m + 1];
    sfx[m] = fx; sfy[m] = fy;
    __syncthreads();
    int p = -1;
    for (int q = 0; q < Md; q++)
        if (q != m && sfx[q] == -fx && sfy[q] == -fy) { p = q; break; }
    sp[m] = p;
    __syncthreads();
    if (m == 0) {
        int cnt = 0;
        for (int mm = 0; mm < Md && cnt < CAP; mm++) {
            const int pp = sp[mm];
            if (pp >= 0 && pp < mm) continue;  // covered by an earlier rep
            g_rep_m[cnt] = mm; g_rep_pair[cnt] = pp;
            g_rep_fx[cnt] = sfx[mm]; g_rep_fy[cnt] = sfy[mm]; cnt++;
        }
        for (int j = cnt; j < CAP; j++) {
            g_rep_m[j] = -1; g_rep_pair[j] = -1;
            g_rep_fx[j] = 0.f; g_rep_fy[j] = 0.f;
        }
    }
}

// ---------------------------------------------------------------------------
// K1 proj: D[c(64)][j2(80)] += X[c][k] * T[j2][k]  over n, bf16 hi/lo.
// (R7 structure: warp = c-tile m16 x j2-half, all 12 ksteps)
// smem: Xs[64][136]h | Ts[80][136]h | xs[64][68]f | sco[64]f2
// ---------------------------------------------------------------------------
#define PSTR 136
#define PSTRW 68
#define TS_OFF (64 * PSTR)
#define XSF_OFF (144 * PSTR * 2)
#define SCO_OFF (XSF_OFF + 64 * 68 * 4)
#define PROJ_SMEM (SCO_OFF + 64 * 8)

__global__ __launch_bounds__(256) void proj_kernel(
    const float* __restrict__ inputs, const float* __restrict__ coords)
{
    extern __shared__ __align__(16) ush sm[];
    uint32_t* Xw = (uint32_t*)sm;
    uint32_t* Tw = (uint32_t*)(sm + TS_OFF);
    float (*xs)[68] = (float(*)[68])((char*)sm + XSF_OFF);
    float2* sco = (float2*)((char*)sm + SCO_OFF);

    const int tid = threadIdx.x, wid = tid >> 5, lane = tid & 31;
    const int g = lane >> 2, tq = lane & 3;
    const int split = blockIdx.x, b = blockIdx.y;

    // zero T tile once (rows 72-79 must stay zero)
    for (int i = tid; i < 80 * PSTRW; i += 256) Tw[i] = 0;

    const int mt = wid >> 1;                 // c tile: c0 = mt*16
    const int nb = (wid & 1) * 5;            // j2 tiles nb..nb+4

    float acc[5][4];
    #pragma unroll
    for (int u = 0; u < 5; u++)
        #pragma unroll
        for (int v = 0; v < 4; v++) acc[u][v] = 0.f;

    const int nbase = split * (Nd / Sp);
    const float2* cin = ((const float2*)coords) + (size_t)b * Nd;

    for (int t = 0; t < PCHUNKS; t++) {
        const int n0 = nbase + t * 64;
        __syncthreads();                     // tiles & xs free
        // stage x [64n][64c]
        const float4* xin4 = (const float4*)(inputs + ((size_t)b * Nd + n0) * Cd);
        #pragma unroll
        for (int r = 0; r < 4; r++) {
            const int idx = tid + 256 * r;
            const float4 v = xin4[idx];
            *(float4*)&xs[idx >> 4][(idx & 15) << 2] = v;
        }
        if (tid < 64) sco[tid] = cin[n0 + tid];
        __syncthreads();

        // X tile: c = tid>>2, n = 2q + 8i (conflict-free column reads)
        {
            const int c = tid >> 2, q = tid & 3;
            #pragma unroll
            for (int i = 0; i < 8; i++) {
                const int n = 2 * q + 8 * i;
                ush h0, l0, h1, l1;
                splitb(xs[n][c], h0, l0);
                splitb(xs[n + 1][c], h1, l1);
                Xw[c * PSTRW + (n >> 1)]      = pk(h0, h1);
                Xw[c * PSTRW + 32 + (n >> 1)] = pk(l0, l1);
            }
        }
        // T tile: 1152 (j, n-pair) items
        for (int e = tid; e < 1152; e += 256) {
            const int j = e >> 5, n = (e & 31) * 2;
            const float fx = g_rep_fx[j], fy = g_rep_fy[j];
            float s0, c0, s1, c1;
            trig_of(sco[n], fx, fy, s0, c0);
            trig_of(sco[n + 1], fx, fy, s1, c1);
            ush ch0, cl0, sh0, sl0, ch1, cl1, sh1, sl1;
            splitb(c0, ch0, cl0); splitb(s0, sh0, sl0);
            splitb(c1, ch1, cl1); splitb(s1, sh1, sl1);
            Tw[j * PSTRW + (n >> 1)]             = pk(ch0, ch1);
            Tw[j * PSTRW + 32 + (n >> 1)]        = pk(cl0, cl1);
            Tw[(36 + j) * PSTRW + (n >> 1)]      = pk(sh0, sh1);
            Tw[(36 + j) * PSTRW + 32 + (n >> 1)] = pk(sl0, sl1);
        }
        __syncthreads();

        // MMA: 12 ksteps = 3 product groups x 4
        #pragma unroll
        for (int gr = 0; gr < 3; gr++) {
            const int kwAb = (gr == 1) ? 32 : 0;     // X lo for group 1
            const int kwBb = (gr == 2) ? 32 : 0;     // T lo for group 2
            #pragma unroll
            for (int s = 0; s < 4; s++) {
                const int kwA = kwAb + 8 * s, kwB = kwBb + 8 * s;
                uint32_t a[4];
                const int ra = (mt * 16 + g) * PSTRW + kwA + tq;
                a[0] = Xw[ra];              a[1] = Xw[ra + 8 * PSTRW];
                a[2] = Xw[ra + 4];          a[3] = Xw[ra + 8 * PSTRW + 4];
                #pragma unroll
                for (int u = 0; u < 5; u++) {
                    uint32_t bb[2];
                    const int rb = ((nb + u) * 8 + g) * PSTRW + kwB + tq;
                    bb[0] = Tw[rb]; bb[1] = Tw[rb + 4];
                    hmma(acc[u], a, bb);
                }
            }
        }
    }

    // epilogue: D[c][j2] -> g_partial[split][b][c][80]
    float* dst = g_partial + (((size_t)split * Bd + b) * Cd) * 80;
    #pragma unroll
    for (int u = 0; u < 5; u++) {
        const int j = (nb + u) * 8 + 2 * tq;
        const int c0 = mt * 16 + g;
        *(float2*)&dst[(size_t)c0 * 80 + j]       = make_float2(acc[u][0], acc[u][1]);
        *(float2*)&dst[(size_t)(c0 + 8) * 80 + j] = make_float2(acc[u][2], acc[u][3]);
    }
}

// ---------------------------------------------------------------------------
// K2a: parallel reduce 512 slices -> 8 (coalesced; deterministic grouping)
// ---------------------------------------------------------------------------
__global__ __launch_bounds__(256) void reduce_kernel() {
    const int idx = blockIdx.x * 256 + threadIdx.x;       // over 8*SLICE
    const int r8 = idx / SLICE;
    const int rem = idx - r8 * SLICE;
    const float* p = g_partial + (size_t)r8 * (Sp / 8) * SLICE + rem;
    float s = 0.f;
    #pragma unroll 8
    for (int i = 0; i < Sp / 8; i++) s += p[(size_t)i * SLICE];
    g_red[idx] = s;
}

// ---------------------------------------------------------------------------
// K2b mix: reduce 8 slices, 1/N + weight + conj fold, emit bf16 hi/lo W
// ---------------------------------------------------------------------------
__global__ __launch_bounds__(256) void mix_kernel(
    const float* __restrict__ wre, const float* __restrict__ wim)
{
    const int idx = blockIdx.x * 256 + threadIdx.x;       // Bd*64*36
    const int b = idx / (Cd * CAP);
    const int rem = idx - b * (Cd * CAP);
    const int c = rem / CAP, j = rem - c * CAP;
    const int m = g_rep_m[j];
    if (m < 0) return;

    float cr = 0.f, si = 0.f;
    const float* p = g_red + ((size_t)b * Cd + c) * 80;
    #pragma unroll
    for (int s = 0; s < 8; s++) {
        cr += p[(size_t)s * SLICE + j];
        si += p[(size_t)s * SLICE + 36 + j];
    }
    const float ci = -si, inv = 1.0f / (float)Nd;
    const float wr = wre[m * Cd + c], wi = wim[m * Cd + c];
    float A2 =  (cr * wr - ci * wi) * inv;
    float B2 = -(cr * wi + ci * wr) * inv;
    const int pp = g_rep_pair[j];
    if (pp >= 0) {
        const float wrp = wre[pp * Cd + c], wip = wim[pp * Cd + c];
        A2 += ( cr * wrp + ci * wip) * inv;
        B2 -= (-cr * wip + ci * wrp) * inv;
    }
    ush ah, al, bh, bl;
    splitb(A2, ah, al); splitb(B2, bh, bl);
    ush* W = g_W + ((size_t)b * Cd + c) * 160;
    W[j] = ah; W[36 + j] = bh; W[80 + j] = al; W[116 + j] = bl;
}

// ---------------------------------------------------------------------------
// K3 recon: D[n(128)][c(64)] = T[n][k] * W[c][k]
// warp = (n32-tile, c32-half): m32n32 per warp, A-frags shared across halves
// smem: Ts[128][168]h | Ws[64][168]h
// ---------------------------------------------------------------------------
#define RSTR 168
#define RSTRW 84
#define WS_OFF (128 * RSTR)
#define RECON_SMEM ((128 + 64) * RSTR * 2)

__global__ __launch_bounds__(256, 2) void recon_kernel(
    const float* __restrict__ coords, float* __restrict__ out)
{
    extern __shared__ __align__(16) ush sm[];
    ush* Ws = sm + WS_OFF;
    uint32_t* Twr = (uint32_t*)sm;
    uint32_t* Wwr = (uint32_t*)Ws;

    const int tid = threadIdx.x, wid = tid >> 5, lane = tid & 31;
    const int g = lane >> 2, tq = lane & 3;
    const int b = blockIdx.y, n0 = blockIdx.x * 128;

    // zero Ts pad words: hi-pad 36..39 (halves 72..79) AND lo-pad 76..79
    // (halves 152..159) — both are read by the kstep loops.
    if (tid < 128) {
        uint32_t* r = Twr + tid * RSTRW;
        r[36] = 0; r[37] = 0; r[38] = 0; r[39] = 0;
        r[76] = 0; r[77] = 0; r[78] = 0; r[79] = 0;
    }
    // W tile: 64 rows x 20 uint4 (g_W pads are statically zero)
    for (int v = tid; v < 1280; v += 256) {
        const int c = v / 20, q2 = v - c * 20;
        const uint4 w = *(const uint4*)(g_W + ((size_t)b * Cd + c) * 160 + q2 * 8);
        *(uint4*)&Ws[c * RSTR + q2 * 8] = w;
    }
    // T tile: packed STS.32, jw-major: 128 n x 18 mode-pair words
    {
        const float2* cbase = ((const float2*)coords) + (size_t)b * Nd + n0;
        #pragma unroll
        for (int i = 0; i < 9; i++) {
            const int e = tid + 256 * i;              // 0..2303
            const int n = e / 18, jw = e - n * 18;
            const float2 cc = cbase[n];
            const int j0 = 2 * jw, j1 = j0 + 1;
            float s0, c0, s1, c1;
            trig_of(cc, g_rep_fx[j0], g_rep_fy[j0], s0, c0);
            trig_of(cc, g_rep_fx[j1], g_rep_fy[j1], s1, c1);
            ush ch0, cl0, sh0, sl0, ch1, cl1, sh1, sl1;
            splitb(c0, ch0, cl0); splitb(s0, sh0, sl0);
            splitb(c1, ch1, cl1); splitb(s1, sh1, sl1);
            uint32_t* r = Twr + n * RSTRW;
            r[jw]      = pk(ch0, ch1);
            r[18 + jw] = pk(sh0, sh1);
            r[40 + jw] = pk(cl0, cl1);
            r[58 + jw] = pk(sl0, sl1);
        }
    }
    __syncthreads();

    const int nt = wid & 3;          // n32 tile: rows nt*32 .. +31
    const int ch = wid >> 2;         // c32 half: col tiles ch*4 .. ch*4+3

    float acc[2][4][4];
    #pragma unroll
    for (int t = 0; t < 2; t++)
        #pragma unroll
        for (int u = 0; u < 4; u++)
            #pragma unroll
            for (int v = 0; v < 4; v++) acc[t][u][v] = 0.f;

    // 15 ksteps = 3 groups x 5; A (m32) shared across the 4 B tiles
    #pragma unroll
    for (int s = 0; s < 15; s++) {
        const int gr = s / 5, s5 = s - gr * 5;
        const int kwA = ((gr == 1) ? 40 : 0) + 8 * s5;   // T lo for group 1
        const int kwB = ((gr == 2) ? 40 : 0) + 8 * s5;   // W lo for group 2
        uint32_t a[2][4];
        #pragma unroll
        for (int tt = 0; tt < 2; tt++) {
            const int ra = (nt * 32 + tt * 16 + g) * RSTRW + kwA + tq;
            a[tt][0] = Twr[ra];             a[tt][1] = Twr[ra + 8 * RSTRW];
            a[tt][2] = Twr[ra + 4];         a[tt][3] = Twr[ra + 8 * RSTRW + 4];
        }
        #pragma unroll
        for (int u = 0; u < 4; u++) {
            uint32_t bb[2];
            const int rb = ((ch * 4 + u) * 8 + g) * RSTRW + kwB + tq;
            bb[0] = Wwr[rb]; bb[1] = Wwr[rb + 4];
            hmma(acc[0][u], a[0], bb);
            hmma(acc[1][u], a[1], bb);
        }
    }

    // epilogue: D[n][c] -> out
    #pragma unroll
    for (int tt = 0; tt < 2; tt++) {
        const int r0 = nt * 32 + tt * 16 + g;
        float* o0 = out + ((size_t)b * Nd + n0 + r0) * Cd;
        float* o1 = o0 + 8 * Cd;
        #pragma unroll
        for (int u = 0; u < 4; u++) {
            const int c = (ch * 4 + u) * 8 + 2 * tq;
            *(float2*)&o0[c] = make_float2(acc[tt][u][0], acc[tt][u][1]);
            *(float2*)&o1[c] = make_float2(acc[tt][u][2], acc[tt][u][3]);
        }
    }
}

// ---------------------------------------------------------------------------
extern "C" void kernel_launch(void* const* d_in, const int* in_sizes, int n_in,
                              void* d_out, int out_size)
{
    const float* inputs = (const float*)d_in[0];
    const float* coords = (const float*)d_in[1];
    const float* wre    = (const float*)d_in[2];
    const float* wim    = (const float*)d_in[3];
    const float* freqs  = (const float*)d_in[4];
    float* out = (float*)d_out;

    cudaFuncSetAttribute(proj_kernel,  cudaFuncAttributeMaxDynamicSharedMemorySize, PROJ_SMEM);
    cudaFuncSetAttribute(recon_kernel, cudaFuncAttributeMaxDynamicSharedMemorySize, RECON_SMEM);

    setup_kernel<<<1, 64>>>(freqs);
    proj_kernel<<<dim3(Sp, Bd), 256, PROJ_SMEM>>>(inputs, coords);
    reduce_kernel<<<(8 * SLICE) / 256, 256>>>();
    mix_kernel<<<(Bd * Cd * CAP) / 256, 256>>>(wre, wim);
    recon_kernel<<<dim3(Nd / 128, Bd), 256, RECON_SMEM>>>(coords, out);
}

// round 13
// speedup vs baseline: 1.3711x; 1.0927x over previous
#include <cuda_runtime.h>
#include <cuda_bf16.h>
#include <cstdint>

#define Bd 8
#define Nd 65536
#define Cd 64
#define Md 64
#define CAP 36
#define Sp 256            // proj splits per batch (4 chunks of 64 n each)
#define PCHUNKS ((Nd / Sp) / 64)
#define SLICE (Bd * Cd * 80)
#define TWOPI 6.283185307179586f

typedef unsigned short ush;

// ---------------- device scratch (no allocation; statically zeroed) --------
__device__ float g_rep_fx[CAP], g_rep_fy[CAP];
__device__ int   g_rep_m[CAP], g_rep_pair[CAP];
__device__ float g_partial[(size_t)Sp * SLICE];          // [split][b][c][80]
__device__ float g_red[(size_t)8 * SLICE];               // [8][b][c][80]
__device__ ush   g_W[(size_t)Bd * Cd * 160];             // [b][c][160]; pads stay 0

// ---------------- helpers ----------------
__device__ __forceinline__ void splitb(float x, ush& h, ush& l) {
    uint32_t u = __float_as_uint(x);
    h = (ush)(u >> 16);                                   // truncation (exact hi)
    __nv_bfloat16 lb = __float2bfloat16(x - __uint_as_float(u & 0xFFFF0000u));
    l = *reinterpret_cast<ush*>(&lb);
}
// hi word of pair: {lo16: trunc16(f0), hi16: trunc16(f1)}
__device__ __forceinline__ uint32_t hi_pair(float f0, float f1) {
    uint32_t r;
    asm("prmt.b32 %0, %1, %2, 0x7632;" : "=r"(r)
        : "r"(__float_as_uint(f0)), "r"(__float_as_uint(f1)));
    return r;
}
// lo word of pair: {lo16: bf16(f0-hi0), hi16: bf16(f1-hi1)}
__device__ __forceinline__ uint32_t lo_pair(float f0, float f1) {
    float l0 = f0 - __uint_as_float(__float_as_uint(f0) & 0xFFFF0000u);
    float l1 = f1 - __uint_as_float(__float_as_uint(f1) & 0xFFFF0000u);
    uint32_t r;
    asm("cvt.rn.bf16x2.f32 %0, %1, %2;" : "=r"(r) : "f"(l1), "f"(l0));
    return r;
}
__device__ __forceinline__ void trig_of2(float cx, float cy, float fx, float fy,
                                         float& s, float& c) {
    float t = cx * fx + cy * fy;                          // integer freqs
    float ph = TWOPI * (t - rintf(t));                    // exact reduce to [-pi,pi]
    __sincosf(ph, &s, &c);
}
// D(16x8,f32) += A(16x16 row,bf16) * B(16x8 col,bf16)
__device__ __forceinline__ void hmma(float* d, const uint32_t* a, const uint32_t* b) {
    asm volatile(
        "mma.sync.aligned.m16n8k16.row.col.f32.bf16.bf16.f32 "
        "{%0,%1,%2,%3},{%4,%5,%6,%7},{%8,%9},{%0,%1,%2,%3};"
        : "+f"(d[0]), "+f"(d[1]), "+f"(d[2]), "+f"(d[3])
        : "r"(a[0]), "r"(a[1]), "r"(a[2]), "r"(a[3]), "r"(b[0]), "r"(b[1]));
}

// ---------------------------------------------------------------------------
// K0: conjugate-pair discovery (parallel; deterministic rep order)
// ---------------------------------------------------------------------------
__global__ void setup_kernel(const float* __restrict__ freqs) {
    __shared__ float sfx[Md], sfy[Md];
    __shared__ int sp[Md];
    const int m = threadIdx.x;                 // 64 threads
    const float fx = freqs[2 * m], fy = freqs[2 * m + 1];
    sfx[m] = fx; sfy[m] = fy;
    __syncthreads();
    int p = -1;
    for (int q = 0; q < Md; q++)
        if (q != m && sfx[q] == -fx && sfy[q] == -fy) { p = q; break; }
    sp[m] = p;
    __syncthreads();
    if (m == 0) {
        int cnt = 0;
        for (int mm = 0; mm < Md && cnt < CAP; mm++) {
            const int pp = sp[mm];
            if (pp >= 0 && pp < mm) continue;  // covered by an earlier rep
            g_rep_m[cnt] = mm; g_rep_pair[cnt] = pp;
            g_rep_fx[cnt] = sfx[mm]; g_rep_fy[cnt] = sfy[mm]; cnt++;
        }
        for (int j = cnt; j < CAP; j++) {
            g_rep_m[j] = -1; g_rep_pair[j] = -1;
            g_rep_fx[j] = 0.f; g_rep_fy[j] = 0.f;
        }
    }
}

// ---------------------------------------------------------------------------
// K1 proj: D[c(64)][j2(80)] += X[c][k] * T[j2][k] over n, bf16 hi/lo.
// Direct gmem->bf16 build (no float staging): lane-permuted so STS is
// conflict-free AND both members of every (n,n+1) k-pair are thread-local.
// smem: Xw[64 c][68 words] | Tw[80 j2][68 words]   (hi words 0-31, lo 32-63)
// ---------------------------------------------------------------------------
#define PSTRW 68
#define PROJ_SMEM ((64 + 80) * PSTRW * 4)

__global__ __launch_bounds__(256, 4) void proj_kernel(
    const float* __restrict__ inputs, const float* __restrict__ coords)
{
    extern __shared__ __align__(16) uint32_t smw[];
    uint32_t* Xw = smw;                        // [64][68]
    uint32_t* Tw = smw + 64 * PSTRW;           // [80][68]

    const int tid = threadIdx.x, wid = tid >> 5, lane = tid & 31;
    const int g = lane >> 2, tq = lane & 3;
    const int split = blockIdx.x, b = blockIdx.y;

    // zero T pad rows 72-79 once (read by MMA, never written)
    for (int i = tid; i < 8 * PSTRW; i += 256) Tw[72 * PSTRW + i] = 0;

    const int mt = wid >> 1;                   // c tile: c0 = mt*16
    const int nb = (wid & 1) * 5;              // j2 tiles nb..nb+4

    float acc[5][4];
    #pragma unroll
    for (int u = 0; u < 5; u++)
        #pragma unroll
        for (int v = 0; v < 4; v++) acc[u][v] = 0.f;

    const int nbase = split * (Nd / Sp);
    const int npl = 4 * wid + tq;              // this lane's n-pair (0..31)

    for (int t = 0; t < PCHUNKS; t++) {
        const int n0 = nbase + t * 64;
        __syncthreads();                       // tiles free (prev MMA done)

        // ---- X build: direct LDG -> pairwise bf16 -> CF STS ----
        {
            const float* xrow = inputs + ((size_t)b * Nd + n0) * Cd;
            const int r0 = 2 * npl;
            #pragma unroll
            for (int ic = 0; ic < 8; ic++) {
                const int c = g + 8 * ic;
                const float f0 = xrow[(size_t)r0 * Cd + c];
                const float f1 = xrow[(size_t)(r0 + 1) * Cd + c];
                Xw[c * PSTRW + npl]      = hi_pair(f0, f1);
                Xw[c * PSTRW + 32 + npl] = lo_pair(f0, f1);
            }
        }
        // ---- T build: 1152 (j, n-pair) items, pairwise conversion ----
        {
            const float* cbase = coords + ((size_t)b * Nd + n0) * 2;
            for (int e = tid; e < 1152; e += 256) {
                const int j = e >> 5, w = e & 31;
                const float4 cc = *(const float4*)(cbase + 4 * w);
                const float fx = g_rep_fx[j], fy = g_rep_fy[j];
                float s0, c0, s1, c1;
                trig_of2(cc.x, cc.y, fx, fy, s0, c0);
                trig_of2(cc.z, cc.w, fx, fy, s1, c1);
                uint32_t* r = Tw + j * PSTRW;
                r[w]      = hi_pair(c0, c1);
                r[32 + w] = lo_pair(c0, c1);
                r += 36 * PSTRW;
                r[w]      = hi_pair(s0, s1);
                r[32 + w] = lo_pair(s0, s1);
            }
        }
        __syncthreads();

        // ---- MMA: 12 ksteps = 3 product groups x 4 ----
        #pragma unroll
        for (int gr = 0; gr < 3; gr++) {
            const int kwAb = (gr == 1) ? 32 : 0;     // X lo for group 1
            const int kwBb = (gr == 2) ? 32 : 0;     // T lo for group 2
            #pragma unroll
            for (int s = 0; s < 4; s++) {
                const int kwA = kwAb + 8 * s, kwB = kwBb + 8 * s;
                uint32_t a[4];
                const int ra = (mt * 16 + g) * PSTRW + kwA + tq;
                a[0] = Xw[ra];              a[1] = Xw[ra + 8 * PSTRW];
                a[2] = Xw[ra + 4];          a[3] = Xw[ra + 8 * PSTRW + 4];
                #pragma unroll
                for (int u = 0; u < 5; u++) {
                    uint32_t bb[2];
                    const int rb = ((nb + u) * 8 + g) * PSTRW + kwB + tq;
                    bb[0] = Tw[rb]; bb[1] = Tw[rb + 4];
                    hmma(acc[u], a, bb);
                }
            }
        }
    }

    // epilogue: D[c][j2] -> g_partial[split][b][c][80]
    float* dst = g_partial + (((size_t)split * Bd + b) * Cd) * 80;
    #pragma unroll
    for (int u = 0; u < 5; u++) {
        const int j = (nb + u) * 8 + 2 * tq;
        const int c0 = mt * 16 + g;
        *(float2*)&dst[(size_t)c0 * 80 + j]       = make_float2(acc[u][0], acc[u][1]);
        *(float2*)&dst[(size_t)(c0 + 8) * 80 + j] = make_float2(acc[u][2], acc[u][3]);
    }
}

// ---------------------------------------------------------------------------
// K2a: parallel reduce Sp slices -> 8 (coalesced; deterministic grouping)
// ---------------------------------------------------------------------------
__global__ __launch_bounds__(256) void reduce_kernel() {
    const int idx = blockIdx.x * 256 + threadIdx.x;       // over 8*SLICE
    const int r8 = idx / SLICE;
    const int rem = idx - r8 * SLICE;
    const float* p = g_partial + (size_t)r8 * (Sp / 8) * SLICE + rem;
    float s = 0.f;
    #pragma unroll 8
    for (int i = 0; i < Sp / 8; i++) s += p[(size_t)i * SLICE];
    g_red[idx] = s;
}

// ---------------------------------------------------------------------------
// K2b mix: reduce 8 slices, 1/N + weight + conj fold, emit bf16 hi/lo W
// ---------------------------------------------------------------------------
__global__ __launch_bounds__(256) void mix_kernel(
    const float* __restrict__ wre, const float* __restrict__ wim)
{
    const int idx = blockIdx.x * 256 + threadIdx.x;       // Bd*64*36
    const int b = idx / (Cd * CAP);
    const int rem = idx - b * (Cd * CAP);
    const int c = rem / CAP, j = rem - c * CAP;
    const int m = g_rep_m[j];
    if (m < 0) return;

    float cr = 0.f, si = 0.f;
    const float* p = g_red + ((size_t)b * Cd + c) * 80;
    #pragma unroll
    for (int s = 0; s < 8; s++) {
        cr += p[(size_t)s * SLICE + j];
        si += p[(size_t)s * SLICE + 36 + j];
    }
    const float ci = -si, inv = 1.0f / (float)Nd;
    const float wr = wre[m * Cd + c], wi = wim[m * Cd + c];
    float A2 =  (cr * wr - ci * wi) * inv;
    float B2 = -(cr * wi + ci * wr) * inv;
    const int pp = g_rep_pair[j];
    if (pp >= 0) {
        const float wrp = wre[pp * Cd + c], wip = wim[pp * Cd + c];
        A2 += ( cr * wrp + ci * wip) * inv;
        B2 -= (-cr * wip + ci * wrp) * inv;
    }
    ush ah, al, bh, bl;
    splitb(A2, ah, al); splitb(B2, bh, bl);
    ush* W = g_W + ((size_t)b * Cd + c) * 160;
    W[j] = ah; W[36 + j] = bh; W[80 + j] = al; W[116 + j] = bl;
}

// ---------------------------------------------------------------------------
// K3 recon: D[n(128)][c(64)] = T[n][k] * W[c][k]
// warp = (n32-tile, c32-half): m32n32 per warp, A-frags shared across halves
// smem: Ts[128][168]h | Ws[64][168]h
// ---------------------------------------------------------------------------
#define RSTR 168
#define RSTRW 84
#define WS_OFF (128 * RSTR)
#define RECON_SMEM ((128 + 64) * RSTR * 2)

__global__ __launch_bounds__(256, 2) void recon_kernel(
    const float* __restrict__ coords, float* __restrict__ out)
{
    extern __shared__ __align__(16) ush sm[];
    ush* Ws = sm + WS_OFF;
    uint32_t* Twr = (uint32_t*)sm;
    uint32_t* Wwr = (uint32_t*)Ws;

    const int tid = threadIdx.x, wid = tid >> 5, lane = tid & 31;
    const int g = lane >> 2, tq = lane & 3;
    const int b = blockIdx.y, n0 = blockIdx.x * 128;

    // zero Ts pad words: hi-pad 36..39 (halves 72..79) AND lo-pad 76..79
    // (halves 152..159) — both are read by the kstep loops.
    if (tid < 128) {
        uint32_t* r = Twr + tid * RSTRW;
        r[36] = 0; r[37] = 0; r[38] = 0; r[39] = 0;
        r[76] = 0; r[77] = 0; r[78] = 0; r[79] = 0;
    }
    // W tile: 64 rows x 20 uint4 (g_W pads are statically zero)
    for (int v = tid; v < 1280; v += 256) {
        const int c = v / 20, q2 = v - c * 20;
        const uint4 w = *(const uint4*)(g_W + ((size_t)b * Cd + c) * 160 + q2 * 8);
        *(uint4*)&Ws[c * RSTR + q2 * 8] = w;
    }
    // T tile: packed STS.32, jw-major: 128 n x 18 mode-pair words
    {
        const float2* cbase = ((const float2*)coords) + (size_t)b * Nd + n0;
        #pragma unroll
        for (int i = 0; i < 9; i++) {
            const int e = tid + 256 * i;              // 0..2303
            const int n = e / 18, jw = e - n * 18;
            const float2 cc = cbase[n];
            const int j0 = 2 * jw, j1 = j0 + 1;
            float s0, c0, s1, c1;
            trig_of2(cc.x, cc.y, g_rep_fx[j0], g_rep_fy[j0], s0, c0);
            trig_of2(cc.x, cc.y, g_rep_fx[j1], g_rep_fy[j1], s1, c1);
            uint32_t* r = Twr + n * RSTRW;
            r[jw]      = hi_pair(c0, c1);
            r[18 + jw] = hi_pair(s0, s1);
            r[40 + jw] = lo_pair(c0, c1);
            r[58 + jw] = lo_pair(s0, s1);
        }
    }
    __syncthreads();

    const int nt = wid & 3;          // n32 tile: rows nt*32 .. +31
    const int ch = wid >> 2;         // c32 half: col tiles ch*4 .. ch*4+3

    float acc[2][4][4];
    #pragma unroll
    for (int t = 0; t < 2; t++)
        #pragma unroll
        for (int u = 0; u < 4; u++)
            #pragma unroll
            for (int v = 0; v < 4; v++) acc[t][u][v] = 0.f;

    // 15 ksteps = 3 groups x 5; A (m32) shared across the 4 B tiles
    #pragma unroll
    for (int s = 0; s < 15; s++) {
        const int gr = s / 5, s5 = s - gr * 5;
        const int kwA = ((gr == 1) ? 40 : 0) + 8 * s5;   // T lo for group 1
        const int kwB = ((gr == 2) ? 40 : 0) + 8 * s5;   // W lo for group 2
        uint32_t a[2][4];
        #pragma unroll
        for (int tt = 0; tt < 2; tt++) {
            const int ra = (nt * 32 + tt * 16 + g) * RSTRW + kwA + tq;
            a[tt][0] = Twr[ra];             a[tt][1] = Twr[ra + 8 * RSTRW];
            a[tt][2] = Twr[ra + 4];         a[tt][3] = Twr[ra + 8 * RSTRW + 4];
        }
        #pragma unroll
        for (int u = 0; u < 4; u++) {
            uint32_t bb[2];
            const int rb = ((ch * 4 + u) * 8 + g) * RSTRW + kwB + tq;
            bb[0] = Wwr[rb]; bb[1] = Wwr[rb + 4];
            hmma(acc[0][u], a[0], bb);
            hmma(acc[1][u], a[1], bb);
        }
    }

    // epilogue: D[n][c] -> out
    #pragma unroll
    for (int tt = 0; tt < 2; tt++) {
        const int r0 = nt * 32 + tt * 16 + g;
        float* o0 = out + ((size_t)b * Nd + n0 + r0) * Cd;
        float* o1 = o0 + 8 * Cd;
        #pragma unroll
        for (int u = 0; u < 4; u++) {
            const int c = (ch * 4 + u) * 8 + 2 * tq;
            *(float2*)&o0[c] = make_float2(acc[tt][u][0], acc[tt][u][1]);
            *(float2*)&o1[c] = make_float2(acc[tt][u][2], acc[tt][u][3]);
        }
    }
}

// ---------------------------------------------------------------------------
extern "C" void kernel_launch(void* const* d_in, const int* in_sizes, int n_in,
                              void* d_out, int out_size)
{
    const float* inputs = (const float*)d_in[0];
    const float* coords = (const float*)d_in[1];
    const float* wre    = (const float*)d_in[2];
    const float* wim    = (const float*)d_in[3];
    const float* freqs  = (const float*)d_in[4];
    float* out = (float*)d_out;

    cudaFuncSetAttribute(proj_kernel,  cudaFuncAttributeMaxDynamicSharedMemorySize, PROJ_SMEM);
    cudaFuncSetAttribute(recon_kernel, cudaFuncAttributeMaxDynamicSharedMemorySize, RECON_SMEM);

    setup_kernel<<<1, 64>>>(freqs);
    proj_kernel<<<dim3(Sp, Bd), 256, PROJ_SMEM>>>(inputs, coords);
    reduce_kernel<<<(8 * SLICE) / 256, 256>>>();
    mix_kernel<<<(Bd * Cd * CAP) / 256, 256>>>(wre, wim);
    recon_kernel<<<dim3(Nd / 128, Bd), 256, RECON_SMEM>>>(coords, out);
}